// round 10
// baseline (speedup 1.0000x reference)
#include <cuda_runtime.h>
#include <cuda_fp16.h>

// Problem dims
#define T_STEPS 8192
#define IN_DIM  512
#define H_DIM   2048
#define G_DIM   8192   // 4*H
#define OUT_DIM 512

// Persistent recurrence kernel config
#define NCTA      148
#define NTHR      512
#define R_MAX     56                       // max W_hh rows per CTA (4*14)
#define SW2_STRIDE_H 1032                  // halves per smem row (2064 B; 2064 % 128 == 16 -> conflict-free ldsm)
#define SW2_BYTES (R_MAX * 2064)           // 115584: smem keeps upper K-half of each quarter
#define SH2_OFF   SW2_BYTES                // h fp16 staging: 4096 B
#define SGATE_OFF (SH2_OFF + 4096)         // [4][64] float partials = 1024 B
#define SC_OFF    (SGATE_OFF + 1024)       // 16 floats cell state
#define SCH_OFF   (SC_OFF + 64)            // 16 ushort packed h
#define SMEM_BYTES (SCH_OFF + 64)          // ~120.8 KB

// GEMM config
#define BM 128
#define BN 128
#define BK 16
#define LDT 132

// ---------------- device scratch ----------------
__device__ __align__(16) float  g_xg[(size_t)T_STEPS * G_DIM];   // x @ W_ih^T + bias
__device__ __align__(16) __half g_whh[(size_t)G_DIM * H_DIM];    // fp16 W_hh
__device__ __align__(16) __half g_hvec[H_DIM];                   // final h (for final_linear)
// Message-passing h publication: payload (weak) + per-CTA flag (release/acquire).
// g_hdat[parity][cta][slot]: slot0 = units 0-7, slot1 = units 8-13 (+pad).
__device__ __align__(16) uint4    g_hdat[2][NCTA][2];
__device__ __align__(16) unsigned g_flag[2][NCTA];               // monotonic step tags

// ---------------- helpers ----------------
__device__ __forceinline__ float sigmoidf_(float x) { return 1.0f / (1.0f + __expf(-x)); }
__device__ __forceinline__ float tanh_accf(float x) {
    float xc = fminf(fmaxf(x, -15.0f), 15.0f);
    float e  = __expf(2.0f * xc);
    return (e - 1.0f) / (e + 1.0f);
}
__device__ __forceinline__ unsigned smem_u32(const void* p) {
    return (unsigned)__cvta_generic_to_shared(p);
}
__device__ __forceinline__ void ldsm4(unsigned& a0, unsigned& a1, unsigned& a2, unsigned& a3,
                                      unsigned addr) {
    asm volatile("ldmatrix.sync.aligned.m8n8.x4.shared.b16 {%0,%1,%2,%3},[%4];"
                 : "=r"(a0), "=r"(a1), "=r"(a2), "=r"(a3) : "r"(addr));
}
__device__ __forceinline__ void mma16816(float& c0, float& c1, float& c2, float& c3,
                                         unsigned a0, unsigned a1, unsigned a2, unsigned a3,
                                         unsigned b0, unsigned b1) {
    asm volatile("mma.sync.aligned.m16n8k16.row.col.f32.f16.f16.f32 "
                 "{%0,%1,%2,%3},{%4,%5,%6,%7},{%8,%9},{%0,%1,%2,%3};"
                 : "+f"(c0), "+f"(c1), "+f"(c2), "+f"(c3)
                 : "r"(a0), "r"(a1), "r"(a2), "r"(a3), "r"(b0), "r"(b1));
}
// Strong scoped handshake ops (PTX acquire/release, gpu scope) + weak payload ops.
__device__ __forceinline__ unsigned ld_acq(const unsigned* p) {
    unsigned v;
    asm volatile("ld.acquire.gpu.global.u32 %0,[%1];" : "=r"(v) : "l"(p) : "memory");
    return v;
}
__device__ __forceinline__ void st_rel(unsigned* p, unsigned v) {
    asm volatile("st.release.gpu.global.u32 [%0],%1;" :: "l"(p), "r"(v) : "memory");
}
__device__ __forceinline__ uint4 ldcg_v4(const uint4* p) {
    uint4 v;
    asm volatile("ld.global.cg.v4.u32 {%0,%1,%2,%3},[%4];"
                 : "=r"(v.x), "=r"(v.y), "=r"(v.z), "=r"(v.w) : "l"(p));
    return v;
}
__device__ __forceinline__ void stcg_v4(uint4* p, uint4 v) {
    asm volatile("st.global.cg.v4.u32 [%0],{%1,%2,%3,%4};"
                 :: "l"(p), "r"(v.x), "r"(v.y), "r"(v.z), "r"(v.w) : "memory");
}
__device__ __forceinline__ void cta_geom(int b, int& J, int& j0) {
    if (b < 124) { J = 14; j0 = b * 14; }
    else         { J = 13; j0 = 124 * 14 + (b - 124) * 13; }
}

// packed f32x2 FMA helpers for the GEMM
__device__ __forceinline__ unsigned long long pk2(float x, float y) {
    unsigned long long r;
    asm("mov.b64 %0, {%1, %2};" : "=l"(r) : "f"(x), "f"(y));
    return r;
}
__device__ __forceinline__ void fma2(unsigned long long& a, unsigned long long m, unsigned long long n) {
    asm("fma.rn.f32x2 %0, %1, %2, %0;" : "+l"(a) : "l"(m), "l"(n));
}
__device__ __forceinline__ void upk2(unsigned long long a, float& x, float& y) {
    asm("mov.b64 {%0, %1}, %2;" : "=f"(x), "=f"(y) : "l"(a));
}

// ---------------- kernel 0: per-launch state init ----------------
// Buffer 0: h0 payload, flag=1. Buffer 1: flag=0. Rewritten every launch
// (graph-replay safety: stale flags would otherwise satisfy future waits).
__global__ void init_state(const float* __restrict__ h0) {
    int i = blockIdx.x * blockDim.x + threadIdx.x;
    if (i < NCTA) { g_flag[0][i] = 1u; g_flag[1][i] = 0u; }
    if (i < NCTA * 2) {
        int b = i >> 1, uu = i & 1;
        int J, j0;
        cta_geom(b, J, j0);
        int cnt = J - 8 * uu; if (cnt > 8) cnt = 8;
        unsigned s[8];
#pragma unroll
        for (int k = 0; k < 8; k++)
            s[k] = (k < cnt) ? (unsigned)__half_as_ushort(__float2half(h0[j0 + 8 * uu + k])) : 0u;
        uint4 v;
        v.x = s[0] | (s[1] << 16);
        v.y = s[2] | (s[3] << 16);
        v.z = s[4] | (s[5] << 16);
        v.w = s[6] | (s[7] << 16);
        g_hdat[0][b][uu] = v;
    }
}

// ---------------- kernel 1: W_hh fp32 -> fp16 ----------------
__global__ void convert_whh(const float* __restrict__ W) {
    const float2* src = (const float2*)W;
    __half2* dst = (__half2*)g_whh;
    size_t n2 = (size_t)G_DIM * H_DIM / 2;
    for (size_t u = (size_t)blockIdx.x * blockDim.x + threadIdx.x; u < n2;
         u += (size_t)gridDim.x * blockDim.x) {
        float2 v = src[u];
        dst[u] = __floats2half2_rn(v.x, v.y);
    }
}

// ---------------- kernel 2: x_gates GEMM (fp32, f32x2 FMA) ----------------
__global__ void __launch_bounds__(256) gemm_xg(const float* __restrict__ A,
                                               const float* __restrict__ B,
                                               const float* __restrict__ bih,
                                               const float* __restrict__ bhh) {
    __shared__ float As[BK * LDT];
    __shared__ float Bs[BK * LDT];
    const int tid = threadIdx.x;
    const int tx = tid & 15, ty = tid >> 4;
    const int bm = blockIdx.y, bn = blockIdx.x;

    unsigned long long acc[8][4];
#pragma unroll
    for (int i = 0; i < 8; i++)
#pragma unroll
        for (int jp = 0; jp < 4; jp++) acc[i][jp] = 0ULL;

    for (int kt = 0; kt < IN_DIM; kt += BK) {
#pragma unroll
        for (int r = 0; r < 2; r++) {
            int id = tid + r * 256;
            int mr = id >> 2, kc = id & 3;
            float4 av = *(const float4*)(A + (size_t)(bm * BM + mr) * IN_DIM + kt + kc * 4);
            As[(kc * 4 + 0) * LDT + mr] = av.x;
            As[(kc * 4 + 1) * LDT + mr] = av.y;
            As[(kc * 4 + 2) * LDT + mr] = av.z;
            As[(kc * 4 + 3) * LDT + mr] = av.w;
            float4 bv = *(const float4*)(B + (size_t)(bn * BN + mr) * IN_DIM + kt + kc * 4);
            Bs[(kc * 4 + 0) * LDT + mr] = bv.x;
            Bs[(kc * 4 + 1) * LDT + mr] = bv.y;
            Bs[(kc * 4 + 2) * LDT + mr] = bv.z;
            Bs[(kc * 4 + 3) * LDT + mr] = bv.w;
        }
        __syncthreads();
#pragma unroll
        for (int k = 0; k < BK; k++) {
            float4 a0 = *(const float4*)(As + k * LDT + ty * 8);
            float4 a1 = *(const float4*)(As + k * LDT + ty * 8 + 4);
            float4 b0 = *(const float4*)(Bs + k * LDT + tx * 8);
            float4 b1 = *(const float4*)(Bs + k * LDT + tx * 8 + 4);
            unsigned long long bb0 = pk2(b0.x, b0.y);
            unsigned long long bb1 = pk2(b0.z, b0.w);
            unsigned long long bb2 = pk2(b1.x, b1.y);
            unsigned long long bb3 = pk2(b1.z, b1.w);
            float aa[8] = {a0.x, a0.y, a0.z, a0.w, a1.x, a1.y, a1.z, a1.w};
#pragma unroll
            for (int i = 0; i < 8; i++) {
                unsigned long long a2 = pk2(aa[i], aa[i]);
                fma2(acc[i][0], a2, bb0);
                fma2(acc[i][1], a2, bb1);
                fma2(acc[i][2], a2, bb2);
                fma2(acc[i][3], a2, bb3);
            }
        }
        __syncthreads();
    }

    int n0 = bn * BN + tx * 8;
    float bias[8];
#pragma unroll
    for (int u = 0; u < 8; u++) bias[u] = bih[n0 + u] + bhh[n0 + u];
#pragma unroll
    for (int i = 0; i < 8; i++) {
        int m = bm * BM + ty * 8 + i;
        float r[8];
#pragma unroll
        for (int jp = 0; jp < 4; jp++) upk2(acc[i][jp], r[2 * jp], r[2 * jp + 1]);
#pragma unroll
        for (int u = 0; u < 8; u++) r[u] += bias[u];
        float4* out = (float4*)(g_xg + (size_t)m * G_DIM + n0);
        out[0] = make_float4(r[0], r[1], r[2], r[3]);
        out[1] = make_float4(r[4], r[5], r[6], r[7]);
    }
}

// ---------------- kernel 3: persistent LSTM recurrence -----------------------
// CTA b owns units [j0, j0+J): 124 x 14 + 24 x 13. Local row lr: gate = lr&3,
// unit = lr>>2; global W_hh row = gate*2048 + j0 + unit.
// 16 warps = 4 row-tiles (16 rows) x 4 K-quarters (512 halves).
// Sync (message passing, proven acq/rel pairing, minimal strong ops):
//   producer lane 0: 2x weak payload stores, then ONE st.release flag = t+2.
//   consumers (2/CTA): spin ONE ld.acquire on that CTA's flag (>= t+1),
//   then one weak v4 payload load + u16 smem scatter.
__global__ void __launch_bounds__(NTHR, 1) lstm_recur(const float* __restrict__ c0) {
    extern __shared__ unsigned char smem_raw[];
    __half* sw    = (__half*)smem_raw;                    // [56][1032] halves (upper K-half per quarter)
    __half* sh2   = (__half*)(smem_raw + SH2_OFF);        // [2048] fp16 h
    float*  sgate = (float*)(smem_raw + SGATE_OFF);       // [4][64] partials
    float*  sc    = (float*)(smem_raw + SC_OFF);          // [16] cell state
    unsigned* schu = (unsigned*)(smem_raw + SCH_OFF);     // [8] packed h words

    const int tid  = threadIdx.x;
    const int lane = tid & 31;
    const int w    = tid >> 5;
    const int b    = blockIdx.x;

    int J, j0;
    cta_geom(b, J, j0);
    const int R = 4 * J;

    // Fill smem with the UPPER K-half of each quarter for all R rows.
    for (int idx = tid; idx < R * 128; idx += NTHR) {
        int lr = idx >> 7, rem = idx & 127;
        int kq4 = rem >> 5, u = rem & 31;
        int grow = (lr & 3) * H_DIM + j0 + (lr >> 2);
        *(uint4*)(sw + lr * SW2_STRIDE_H + kq4 * 256 + u * 8) =
            *(const uint4*)(g_whh + (size_t)grow * H_DIM + kq4 * 512 + 256 + u * 8);
    }
    if (tid < J) sc[tid] = c0[j0 + tid];

    const int tw = w & 3, kq = w >> 2;

    // A-fragments for k16-steps 0..15 of this warp's quarter, in registers.
    unsigned arg[64];
    {
        int r0l = 16 * tw + (lane >> 2);     if (r0l >= R) r0l = 0;
        int r1l = 16 * tw + (lane >> 2) + 8; if (r1l >= R) r1l = 0;
        int g0 = (r0l & 3) * H_DIM + j0 + (r0l >> 2);
        int g1 = (r1l & 3) * H_DIM + j0 + (r1l >> 2);
        const unsigned* p0 = (const unsigned*)(g_whh + (size_t)g0 * H_DIM + kq * 512 + (lane & 3) * 2);
        const unsigned* p1 = (const unsigned*)(g_whh + (size_t)g1 * H_DIM + kq * 512 + (lane & 3) * 2);
#pragma unroll
        for (int j = 0; j < 16; j++) {
            arg[4 * j + 0] = p0[j * 8];
            arg[4 * j + 1] = p1[j * 8];
            arg[4 * j + 2] = p0[j * 8 + 4];
            arg[4 * j + 3] = p1[j * 8 + 4];
        }
    }
    __syncthreads();

    // A-ldsm base (smem steps) and broadcast-B base.
    const int r_l   = 16 * tw + (lane & 15);
    const int r_eff = (r_l < R) ? r_l : 0;
    const unsigned abase = smem_u32(sw) + (unsigned)r_eff * 2064 + (unsigned)kq * 512
                         + ((lane >> 4) * 16);
    const unsigned bbase = smem_u32(sh2) + (unsigned)kq * 1024 + ((lane >> 3) * 16);

    const int  g_row = 16 * tw + (lane >> 2);
    const bool ok_lo = ((lane & 3) == 0) && (g_row < R);
    const bool ok_hi = ((lane & 3) == 0) && (g_row + 8 < R);

    // Consumer geometry: threads 0..295, 2 per producer CTA.
    const int cb = tid >> 1, uu = tid & 1;
    int Jc = 0, j0c = 0, cntc = 0;
    if (tid < 2 * NCTA) {
        cta_geom(cb, Jc, j0c);
        cntc = Jc - 8 * uu; if (cntc > 8) cntc = 8;
    }

    int p = 0;
    for (int t = 0; t < T_STEPS; t++) {
        // x_gates prefetch for this step (independent of h; overlaps the poll).
        float xgi = 0.f, xgf = 0.f, xgg = 0.f, xgo = 0.f;
        if (tid < J) {
            const float* xg = g_xg + (size_t)t * G_DIM + j0 + tid;
            xgi = __ldcg(xg);
            xgf = __ldcg(xg + H_DIM);
            xgg = __ldcg(xg + 2 * H_DIM);
            xgo = __ldcg(xg + 3 * H_DIM);
        }
        // Acquire-spin on this thread's producer flag, then load + scatter payload.
        if (tid < 2 * NCTA) {
            const unsigned want = (unsigned)(t + 1);
            while (ld_acq(&g_flag[p][cb]) < want) { }
            uint4 v = ldcg_v4(&g_hdat[p][cb][uu]);
            unsigned short* d = (unsigned short*)sh2 + j0c + 8 * uu;
            unsigned short s[8];
            s[0] = (unsigned short)(v.x & 0xffffu); s[1] = (unsigned short)(v.x >> 16);
            s[2] = (unsigned short)(v.y & 0xffffu); s[3] = (unsigned short)(v.y >> 16);
            s[4] = (unsigned short)(v.z & 0xffffu); s[5] = (unsigned short)(v.z >> 16);
            s[6] = (unsigned short)(v.w & 0xffffu); s[7] = (unsigned short)(v.w >> 16);
#pragma unroll
            for (int k = 0; k < 8; k++)
                if (k < cntc) d[k] = s[k];
        }
        __syncthreads();

        // Tensor-core matvec.
        float cA0 = 0.f, cA1 = 0.f, cA2 = 0.f, cA3 = 0.f;
        float cB0 = 0.f, cB1 = 0.f, cB2 = 0.f, cB3 = 0.f;
#pragma unroll
        for (int pr = 0; pr < 8; pr++) {
            unsigned t0, t1, t2, t3;
            ldsm4(t0, t1, t2, t3, bbase + pr * 64);
            mma16816(cA0, cA1, cA2, cA3,
                     arg[8 * pr + 0], arg[8 * pr + 1], arg[8 * pr + 2], arg[8 * pr + 3], t0, t1);
            mma16816(cB0, cB1, cB2, cB3,
                     arg[8 * pr + 4], arg[8 * pr + 5], arg[8 * pr + 6], arg[8 * pr + 7], t2, t3);
        }
#pragma unroll
        for (int pr = 0; pr < 8; pr++) {
            unsigned a0, a1, a2, a3, a4, a5, a6, a7, t0, t1, t2, t3;
            ldsm4(a0, a1, a2, a3, abase + pr * 64);
            ldsm4(a4, a5, a6, a7, abase + pr * 64 + 32);
            ldsm4(t0, t1, t2, t3, bbase + 512 + pr * 64);
            mma16816(cA0, cA1, cA2, cA3, a0, a1, a2, a3, t0, t1);
            mma16816(cB0, cB1, cB2, cB3, a4, a5, a6, a7, t2, t3);
        }
        float d0 = cA0 + cB0;
        float d2 = cA2 + cB2;
        if (ok_lo) sgate[kq * 64 + g_row] = d0;
        if (ok_hi) sgate[kq * 64 + g_row + 8] = d2;
        __syncthreads();

        // Cell update (warp 0 threads own the J units) + single-thread publish.
        if (w == 0) {
            if (tid < J) {
                int lr = tid * 4;
                float gi = sgate[lr + 0] + sgate[64 + lr + 0] + sgate[128 + lr + 0] + sgate[192 + lr + 0] + xgi;
                float gf = sgate[lr + 1] + sgate[64 + lr + 1] + sgate[128 + lr + 1] + sgate[192 + lr + 1] + xgf;
                float gg = sgate[lr + 2] + sgate[64 + lr + 2] + sgate[128 + lr + 2] + sgate[192 + lr + 2] + xgg;
                float go = sgate[lr + 3] + sgate[64 + lr + 3] + sgate[128 + lr + 3] + sgate[192 + lr + 3] + xgo;
                float i_ = sigmoidf_(gi);
                float f_ = sigmoidf_(gf);
                float g_ = tanh_accf(gg);
                float o_ = sigmoidf_(go);
                float c = f_ * sc[tid] + i_ * g_;
                sc[tid] = c;
                float h = o_ * tanh_accf(c);
                unsigned short hs = __half_as_ushort(__float2half(h));
                ((unsigned short*)schu)[tid] = hs;
                if (t == T_STEPS - 1) g_hvec[j0 + tid] = __ushort_as_half(hs);
            }
            __syncwarp();
            if (lane == 0) {
                // Lane 0 issues BOTH payload stores then the release flag:
                // release orders this thread's prior weak stores at gpu scope.
                uint4 v0 = make_uint4(schu[0], schu[1], schu[2], schu[3]);
                uint4 v1 = make_uint4(schu[4], schu[5], schu[6], 0u);
                stcg_v4(&g_hdat[p ^ 1][b][0], v0);
                stcg_v4(&g_hdat[p ^ 1][b][1], v1);
                st_rel(&g_flag[p ^ 1][b], (unsigned)(t + 2));
            }
        }
        p ^= 1;
    }
}

// ---------------- kernel 4: final linear on h_last (fp16) ----------------
__global__ void __launch_bounds__(256) final_linear(const float* __restrict__ Wl,
                                                    const float* __restrict__ bl,
                                                    float* __restrict__ out) {
    int wid = threadIdx.x >> 5, ln = threadIdx.x & 31;
    int o = blockIdx.x * 8 + wid;
    const float4* w4 = (const float4*)(Wl + (size_t)o * H_DIM);
    const uint2* h2 = (const uint2*)g_hvec;
    float s = 0.f;
#pragma unroll
    for (int i = 0; i < 16; i++) {
        float4 wv = __ldg(w4 + i * 32 + ln);
        uint2 hv = h2[i * 32 + ln];
        float2 h0 = __half22float2(*(__half2*)&hv.x);
        float2 h1 = __half22float2(*(__half2*)&hv.y);
        s += wv.x * h0.x + wv.y * h0.y + wv.z * h1.x + wv.w * h1.y;
    }
#pragma unroll
    for (int sft = 16; sft >= 1; sft >>= 1) s += __shfl_xor_sync(0xffffffffu, s, sft);
    if (ln == 0) out[o] = s + bl[o];
}

// ---------------- launcher ----------------
extern "C" void kernel_launch(void* const* d_in, const int* in_sizes, int n_in,
                              void* d_out, int out_size) {
    const float* seq  = (const float*)d_in[0];
    const float* Wih  = (const float*)d_in[1];
    const float* Whh  = (const float*)d_in[2];
    const float* bih  = (const float*)d_in[3];
    const float* bhh  = (const float*)d_in[4];
    const float* h0   = (const float*)d_in[5];
    const float* c0   = (const float*)d_in[6];
    const float* Wlin = (const float*)d_in[7];
    const float* blin = (const float*)d_in[8];
    float* out = (float*)d_out;

    cudaFuncSetAttribute(lstm_recur, cudaFuncAttributeMaxDynamicSharedMemorySize, SMEM_BYTES);

    init_state<<<2, 256>>>(h0);
    convert_whh<<<2048, 256>>>(Whh);
    gemm_xg<<<dim3(G_DIM / BN, T_STEPS / BM), 256>>>(seq, Wih, bih, bhh);
    lstm_recur<<<NCTA, NTHR, SMEM_BYTES>>>(c0);
    final_linear<<<OUT_DIM / 8, 256>>>(Wlin, blin, out);
}

// round 11
// speedup vs baseline: 3.1829x; 3.1829x over previous
#include <cuda_runtime.h>
#include <cuda_fp16.h>

// Problem dims
#define T_STEPS 8192
#define IN_DIM  512
#define H_DIM   2048
#define G_DIM   8192   // 4*H
#define OUT_DIM 512

// Persistent recurrence kernel config
#define NCTA      148
#define NTHR      512
#define R_MAX     56                       // max W_hh rows per CTA (4*14)
#define SW2_STRIDE_H 1032                  // halves per smem row (2064 B; 2064 % 128 == 16 -> conflict-free ldsm)
#define SW2_BYTES (R_MAX * 2064)           // 115584: smem keeps upper K-half of each quarter
#define SH2_OFF   SW2_BYTES                // h fp16 staging: 4096 B
#define SGATE_OFF (SH2_OFF + 4096)         // [4][64] float partials = 1024 B
#define SC_OFF    (SGATE_OFF + 1024)       // 16 floats cell state
#define SMEM_BYTES (SC_OFF + 64)           // ~120.8 KB

// GEMM config
#define BM 128
#define BN 128
#define BK 16
#define LDT 132

// ---------------- device scratch ----------------
__device__ __align__(16) float  g_xg[(size_t)T_STEPS * G_DIM];   // x @ W_ih^T + bias
__device__ __align__(16) __half g_whh[(size_t)G_DIM * H_DIM];    // fp16 W_hh
__device__ __align__(16) __half g_hvec[2][H_DIM];                // double-buffered fp16 hidden
__device__ unsigned g_bar;                                       // release/acquire step counter

// ---------------- helpers ----------------
__device__ __forceinline__ float sigmoidf_(float x) { return 1.0f / (1.0f + __expf(-x)); }
__device__ __forceinline__ float tanh_accf(float x) {
    float xc = fminf(fmaxf(x, -15.0f), 15.0f);
    float e  = __expf(2.0f * xc);
    return (e - 1.0f) / (e + 1.0f);
}
__device__ __forceinline__ unsigned smem_u32(const void* p) {
    return (unsigned)__cvta_generic_to_shared(p);
}
__device__ __forceinline__ void ldsm4(unsigned& a0, unsigned& a1, unsigned& a2, unsigned& a3,
                                      unsigned addr) {
    asm volatile("ldmatrix.sync.aligned.m8n8.x4.shared.b16 {%0,%1,%2,%3},[%4];"
                 : "=r"(a0), "=r"(a1), "=r"(a2), "=r"(a3) : "r"(addr));
}
__device__ __forceinline__ void mma16816(float& c0, float& c1, float& c2, float& c3,
                                         unsigned a0, unsigned a1, unsigned a2, unsigned a3,
                                         unsigned b0, unsigned b1) {
    asm volatile("mma.sync.aligned.m16n8k16.row.col.f32.f16.f16.f32 "
                 "{%0,%1,%2,%3},{%4,%5,%6,%7},{%8,%9},{%0,%1,%2,%3};"
                 : "+f"(c0), "+f"(c1), "+f"(c2), "+f"(c3)
                 : "r"(a0), "r"(a1), "r"(a2), "r"(a3), "r"(b0), "r"(b1));
}
// Strong scoped ops: one acquire-spinner per CTA + fence-folded release arrival.
__device__ __forceinline__ unsigned ld_acq(const unsigned* p) {
    unsigned v;
    asm volatile("ld.acquire.gpu.global.u32 %0,[%1];" : "=r"(v) : "l"(p) : "memory");
    return v;
}
__device__ __forceinline__ void red_add_rel(unsigned* p, unsigned v) {
    asm volatile("red.add.release.gpu.global.u32 [%0],%1;" :: "l"(p), "r"(v) : "memory");
}
__device__ __forceinline__ uint4 ldcg_v4(const uint4* p) {
    uint4 v;
    asm volatile("ld.global.cg.v4.u32 {%0,%1,%2,%3},[%4];"
                 : "=r"(v.x), "=r"(v.y), "=r"(v.z), "=r"(v.w) : "l"(p));
    return v;
}
__device__ __forceinline__ void cta_geom(int b, int& J, int& j0) {
    if (b < 124) { J = 14; j0 = b * 14; }
    else         { J = 13; j0 = 124 * 14 + (b - 124) * 13; }
}

// packed f32x2 FMA helpers for the GEMM
__device__ __forceinline__ unsigned long long pk2(float x, float y) {
    unsigned long long r;
    asm("mov.b64 %0, {%1, %2};" : "=l"(r) : "f"(x), "f"(y));
    return r;
}
__device__ __forceinline__ void fma2(unsigned long long& a, unsigned long long m, unsigned long long n) {
    asm("fma.rn.f32x2 %0, %1, %2, %0;" : "+l"(a) : "l"(m), "l"(n));
}
__device__ __forceinline__ void upk2(unsigned long long a, float& x, float& y) {
    asm("mov.b64 {%0, %1}, %2;" : "=f"(x), "=f"(y) : "l"(a));
}

// ---------------- kernel 0: per-launch state init ----------------
__global__ void init_state(const float* __restrict__ h0) {
    int i = blockIdx.x * blockDim.x + threadIdx.x;
    if (i < H_DIM) g_hvec[0][i] = __float2half(h0[i]);
    if (i == 0) g_bar = 0u;
}

// ---------------- kernel 1: W_hh fp32 -> fp16 ----------------
__global__ void convert_whh(const float* __restrict__ W) {
    const float2* src = (const float2*)W;
    __half2* dst = (__half2*)g_whh;
    size_t n2 = (size_t)G_DIM * H_DIM / 2;
    for (size_t u = (size_t)blockIdx.x * blockDim.x + threadIdx.x; u < n2;
         u += (size_t)gridDim.x * blockDim.x) {
        float2 v = src[u];
        dst[u] = __floats2half2_rn(v.x, v.y);
    }
}

// ---------------- kernel 2: x_gates GEMM (fp32, f32x2 FMA) ----------------
__global__ void __launch_bounds__(256) gemm_xg(const float* __restrict__ A,
                                               const float* __restrict__ B,
                                               const float* __restrict__ bih,
                                               const float* __restrict__ bhh) {
    __shared__ float As[BK * LDT];
    __shared__ float Bs[BK * LDT];
    const int tid = threadIdx.x;
    const int tx = tid & 15, ty = tid >> 4;
    const int bm = blockIdx.y, bn = blockIdx.x;

    unsigned long long acc[8][4];
#pragma unroll
    for (int i = 0; i < 8; i++)
#pragma unroll
        for (int jp = 0; jp < 4; jp++) acc[i][jp] = 0ULL;

    for (int kt = 0; kt < IN_DIM; kt += BK) {
#pragma unroll
        for (int r = 0; r < 2; r++) {
            int id = tid + r * 256;
            int mr = id >> 2, kc = id & 3;
            float4 av = *(const float4*)(A + (size_t)(bm * BM + mr) * IN_DIM + kt + kc * 4);
            As[(kc * 4 + 0) * LDT + mr] = av.x;
            As[(kc * 4 + 1) * LDT + mr] = av.y;
            As[(kc * 4 + 2) * LDT + mr] = av.z;
            As[(kc * 4 + 3) * LDT + mr] = av.w;
            float4 bv = *(const float4*)(B + (size_t)(bn * BN + mr) * IN_DIM + kt + kc * 4);
            Bs[(kc * 4 + 0) * LDT + mr] = bv.x;
            Bs[(kc * 4 + 1) * LDT + mr] = bv.y;
            Bs[(kc * 4 + 2) * LDT + mr] = bv.z;
            Bs[(kc * 4 + 3) * LDT + mr] = bv.w;
        }
        __syncthreads();
#pragma unroll
        for (int k = 0; k < BK; k++) {
            float4 a0 = *(const float4*)(As + k * LDT + ty * 8);
            float4 a1 = *(const float4*)(As + k * LDT + ty * 8 + 4);
            float4 b0 = *(const float4*)(Bs + k * LDT + tx * 8);
            float4 b1 = *(const float4*)(Bs + k * LDT + tx * 8 + 4);
            unsigned long long bb0 = pk2(b0.x, b0.y);
            unsigned long long bb1 = pk2(b0.z, b0.w);
            unsigned long long bb2 = pk2(b1.x, b1.y);
            unsigned long long bb3 = pk2(b1.z, b1.w);
            float aa[8] = {a0.x, a0.y, a0.z, a0.w, a1.x, a1.y, a1.z, a1.w};
#pragma unroll
            for (int i = 0; i < 8; i++) {
                unsigned long long a2 = pk2(aa[i], aa[i]);
                fma2(acc[i][0], a2, bb0);
                fma2(acc[i][1], a2, bb1);
                fma2(acc[i][2], a2, bb2);
                fma2(acc[i][3], a2, bb3);
            }
        }
        __syncthreads();
    }

    int n0 = bn * BN + tx * 8;
    float bias[8];
#pragma unroll
    for (int u = 0; u < 8; u++) bias[u] = bih[n0 + u] + bhh[n0 + u];
#pragma unroll
    for (int i = 0; i < 8; i++) {
        int m = bm * BM + ty * 8 + i;
        float r[8];
#pragma unroll
        for (int jp = 0; jp < 4; jp++) upk2(acc[i][jp], r[2 * jp], r[2 * jp + 1]);
#pragma unroll
        for (int u = 0; u < 8; u++) r[u] += bias[u];
        float4* out = (float4*)(g_xg + (size_t)m * G_DIM + n0);
        out[0] = make_float4(r[0], r[1], r[2], r[3]);
        out[1] = make_float4(r[4], r[5], r[6], r[7]);
    }
}

// ---------------- kernel 3: persistent LSTM recurrence -----------------------
// Round-6 skeleton (proven) with cheaper ordering:
//   publish: warp-0 h stores -> __syncwarp -> lane0 red.add.release.gpu
//   detect:  tid 0 ld.acquire.gpu spin (ONE spinner per CTA) -> __syncthreads
//   h reads: weak __ldcg, ordered by the acquire/release pair.
__global__ void __launch_bounds__(NTHR, 1) lstm_recur(const float* __restrict__ c0) {
    extern __shared__ unsigned char smem_raw[];
    __half* sw    = (__half*)smem_raw;                    // [56][1032] halves (upper K-half per quarter)
    __half* sh2   = (__half*)(smem_raw + SH2_OFF);        // [2048] fp16 h
    float*  sgate = (float*)(smem_raw + SGATE_OFF);       // [4][64] partials
    float*  sc    = (float*)(smem_raw + SC_OFF);          // [16] cell state

    const int tid  = threadIdx.x;
    const int lane = tid & 31;
    const int w    = tid >> 5;
    const int b    = blockIdx.x;

    int J, j0;
    cta_geom(b, J, j0);
    const int R = 4 * J;

    // Fill smem with the UPPER K-half of each quarter for all R rows.
    for (int idx = tid; idx < R * 128; idx += NTHR) {
        int lr = idx >> 7, rem = idx & 127;
        int kq4 = rem >> 5, u = rem & 31;
        int grow = (lr & 3) * H_DIM + j0 + (lr >> 2);
        *(uint4*)(sw + lr * SW2_STRIDE_H + kq4 * 256 + u * 8) =
            *(const uint4*)(g_whh + (size_t)grow * H_DIM + kq4 * 512 + 256 + u * 8);
    }
    if (tid < J) sc[tid] = c0[j0 + tid];

    const int tw = w & 3, kq = w >> 2;

    // A-fragments for k16-steps 0..15 of this warp's quarter, in registers.
    unsigned arg[64];
    {
        int r0l = 16 * tw + (lane >> 2);     if (r0l >= R) r0l = 0;
        int r1l = 16 * tw + (lane >> 2) + 8; if (r1l >= R) r1l = 0;
        int g0 = (r0l & 3) * H_DIM + j0 + (r0l >> 2);
        int g1 = (r1l & 3) * H_DIM + j0 + (r1l >> 2);
        const unsigned* p0 = (const unsigned*)(g_whh + (size_t)g0 * H_DIM + kq * 512 + (lane & 3) * 2);
        const unsigned* p1 = (const unsigned*)(g_whh + (size_t)g1 * H_DIM + kq * 512 + (lane & 3) * 2);
#pragma unroll
        for (int j = 0; j < 16; j++) {
            arg[4 * j + 0] = p0[j * 8];
            arg[4 * j + 1] = p1[j * 8];
            arg[4 * j + 2] = p0[j * 8 + 4];
            arg[4 * j + 3] = p1[j * 8 + 4];
        }
    }
    __syncthreads();

    // A-ldsm base (smem steps) and broadcast-B base.
    const int r_l   = 16 * tw + (lane & 15);
    const int r_eff = (r_l < R) ? r_l : 0;
    const unsigned abase = smem_u32(sw) + (unsigned)r_eff * 2064 + (unsigned)kq * 512
                         + ((lane >> 4) * 16);
    const unsigned bbase = smem_u32(sh2) + (unsigned)kq * 1024 + ((lane >> 3) * 16);

    const int  g_row = 16 * tw + (lane >> 2);
    const bool ok_lo = ((lane & 3) == 0) && (g_row < R);
    const bool ok_hi = ((lane & 3) == 0) && (g_row + 8 < R);

    int p = 0;
    for (int t = 0; t < T_STEPS; t++) {
        // x_gates prefetch for this step (independent of h; overlaps the spin).
        float xgi = 0.f, xgf = 0.f, xgg = 0.f, xgo = 0.f;
        if (tid < J) {
            const float* xg = g_xg + (size_t)t * G_DIM + j0 + tid;
            xgi = __ldcg(xg);
            xgf = __ldcg(xg + H_DIM);
            xgg = __ldcg(xg + 2 * H_DIM);
            xgo = __ldcg(xg + 3 * H_DIM);
        }
        // Wait for all CTAs' step-(t-1) publishes: ONE acquire spinner per CTA.
        if (tid == 0) {
            const unsigned target = (unsigned)t * (unsigned)NCTA;
            while (ld_acq(&g_bar) < target) { }
        }
        __syncthreads();
        // Stage h (fp16) from L2 into SMEM: 256 threads x 16 B.
        if (tid < 256) {
            uint4 v = ldcg_v4(((const uint4*)g_hvec[p]) + tid);
            *(uint4*)(sh2 + tid * 8) = v;
        }
        __syncthreads();

        // Tensor-core matvec.
        float cA0 = 0.f, cA1 = 0.f, cA2 = 0.f, cA3 = 0.f;
        float cB0 = 0.f, cB1 = 0.f, cB2 = 0.f, cB3 = 0.f;
#pragma unroll
        for (int pr = 0; pr < 8; pr++) {
            unsigned t0, t1, t2, t3;
            ldsm4(t0, t1, t2, t3, bbase + pr * 64);
            mma16816(cA0, cA1, cA2, cA3,
                     arg[8 * pr + 0], arg[8 * pr + 1], arg[8 * pr + 2], arg[8 * pr + 3], t0, t1);
            mma16816(cB0, cB1, cB2, cB3,
                     arg[8 * pr + 4], arg[8 * pr + 5], arg[8 * pr + 6], arg[8 * pr + 7], t2, t3);
        }
#pragma unroll
        for (int pr = 0; pr < 8; pr++) {
            unsigned a0, a1, a2, a3, a4, a5, a6, a7, t0, t1, t2, t3;
            ldsm4(a0, a1, a2, a3, abase + pr * 64);
            ldsm4(a4, a5, a6, a7, abase + pr * 64 + 32);
            ldsm4(t0, t1, t2, t3, bbase + 512 + pr * 64);
            mma16816(cA0, cA1, cA2, cA3, a0, a1, a2, a3, t0, t1);
            mma16816(cB0, cB1, cB2, cB3, a4, a5, a6, a7, t2, t3);
        }
        float d0 = cA0 + cB0;
        float d2 = cA2 + cB2;
        if (ok_lo) sgate[kq * 64 + g_row] = d0;
        if (ok_hi) sgate[kq * 64 + g_row + 8] = d2;
        __syncthreads();

        // Cell update (warp 0 owns the J units) + release arrival by lane 0.
        if (tid < J) {
            int lr = tid * 4;
            float gi = sgate[lr + 0] + sgate[64 + lr + 0] + sgate[128 + lr + 0] + sgate[192 + lr + 0] + xgi;
            float gf = sgate[lr + 1] + sgate[64 + lr + 1] + sgate[128 + lr + 1] + sgate[192 + lr + 1] + xgf;
            float gg = sgate[lr + 2] + sgate[64 + lr + 2] + sgate[128 + lr + 2] + sgate[192 + lr + 2] + xgg;
            float go = sgate[lr + 3] + sgate[64 + lr + 3] + sgate[128 + lr + 3] + sgate[192 + lr + 3] + xgo;
            float i_ = sigmoidf_(gi);
            float f_ = sigmoidf_(gf);
            float g_ = tanh_accf(gg);
            float o_ = sigmoidf_(go);
            float c = f_ * sc[tid] + i_ * g_;
            sc[tid] = c;
            float h = o_ * tanh_accf(c);
            unsigned short hs = __half_as_ushort(__float2half(h));
            asm volatile("st.global.cg.u16 [%0], %1;"
                         :: "l"(&g_hvec[p ^ 1][j0 + tid]), "h"(hs) : "memory");
        }
        if (w == 0) {
            __syncwarp();                       // warp-scope mem sync: h stores visible to lane 0
            if (lane == 0) red_add_rel(&g_bar, 1u);  // release elevates to gpu scope
        }
        p ^= 1;
    }
}

// ---------------- kernel 4: final linear on h_last (fp16, buffer 0) ----------
__global__ void __launch_bounds__(256) final_linear(const float* __restrict__ Wl,
                                                    const float* __restrict__ bl,
                                                    float* __restrict__ out) {
    int wid = threadIdx.x >> 5, ln = threadIdx.x & 31;
    int o = blockIdx.x * 8 + wid;
    const float4* w4 = (const float4*)(Wl + (size_t)o * H_DIM);
    const uint2* h2 = (const uint2*)g_hvec[0];
    float s = 0.f;
#pragma unroll
    for (int i = 0; i < 16; i++) {
        float4 wv = __ldg(w4 + i * 32 + ln);
        uint2 hv = h2[i * 32 + ln];
        float2 h0 = __half22float2(*(__half2*)&hv.x);
        float2 h1 = __half22float2(*(__half2*)&hv.y);
        s += wv.x * h0.x + wv.y * h0.y + wv.z * h1.x + wv.w * h1.y;
    }
#pragma unroll
    for (int sft = 16; sft >= 1; sft >>= 1) s += __shfl_xor_sync(0xffffffffu, s, sft);
    if (ln == 0) out[o] = s + bl[o];
}

// ---------------- launcher ----------------
extern "C" void kernel_launch(void* const* d_in, const int* in_sizes, int n_in,
                              void* d_out, int out_size) {
    const float* seq  = (const float*)d_in[0];
    const float* Wih  = (const float*)d_in[1];
    const float* Whh  = (const float*)d_in[2];
    const float* bih  = (const float*)d_in[3];
    const float* bhh  = (const float*)d_in[4];
    const float* h0   = (const float*)d_in[5];
    const float* c0   = (const float*)d_in[6];
    const float* Wlin = (const float*)d_in[7];
    const float* blin = (const float*)d_in[8];
    float* out = (float*)d_out;

    cudaFuncSetAttribute(lstm_recur, cudaFuncAttributeMaxDynamicSharedMemorySize, SMEM_BYTES);

    init_state<<<8, 256>>>(h0);
    convert_whh<<<2048, 256>>>(Whh);
    gemm_xg<<<dim3(G_DIM / BN, T_STEPS / BM), 256>>>(seq, Wih, bih, bhh);
    lstm_recur<<<NCTA, NTHR, SMEM_BYTES>>>(c0);
    final_linear<<<OUT_DIM / 8, 256>>>(Wlin, blin, out);
}

// round 12
// speedup vs baseline: 3.4716x; 1.0907x over previous
#include <cuda_runtime.h>
#include <cuda_fp16.h>

// Problem dims
#define T_STEPS 8192
#define IN_DIM  512
#define H_DIM   2048
#define G_DIM   8192   // 4*H
#define OUT_DIM 512

// Persistent recurrence kernel config
#define NCTA      148
#define NTHR      512
#define R_MAX     56                       // max W_hh rows per CTA (4*14)
#define SWROW_B   2064                     // smem bytes per W row (1024 halves + 16B pad; %128==16 -> conflict-free ldsm)
#define SW2_BYTES (R_MAX * SWROW_B)        // 115584 (upper 64 halves of each 128-half K-slice)
#define SH2_OFF   SW2_BYTES                // h fp16 staging: 4096 B
#define SGATE_OFF (SH2_OFF + 4096)        // [64][SGS] float partials
#define SGS       20                       // sgate row stride in floats (80B: 16B-aligned, conflict-spread)
#define SC_OFF    (SGATE_OFF + 64 * SGS * 4)   // 16 floats cell state
#define SMEM_BYTES (SC_OFF + 64)           // ~122 KB

// GEMM config
#define BM 128
#define BN 128
#define BK 16
#define LDT 132

// ---------------- device scratch ----------------
__device__ __align__(16) float  g_xg[(size_t)T_STEPS * G_DIM];   // x @ W_ih^T + bias
__device__ __align__(16) __half g_whh[(size_t)G_DIM * H_DIM];    // fp16 W_hh
__device__ __align__(16) __half g_hvec[2][H_DIM];                // double-buffered fp16 hidden
__device__ unsigned g_bar;                                       // release/acquire step counter

// ---------------- helpers ----------------
__device__ __forceinline__ float sigmoidf_(float x) { return 1.0f / (1.0f + __expf(-x)); }
__device__ __forceinline__ float tanh_accf(float x) {
    float xc = fminf(fmaxf(x, -15.0f), 15.0f);
    float e  = __expf(2.0f * xc);
    return (e - 1.0f) / (e + 1.0f);
}
__device__ __forceinline__ unsigned smem_u32(const void* p) {
    return (unsigned)__cvta_generic_to_shared(p);
}
__device__ __forceinline__ void ldsm4(unsigned& a0, unsigned& a1, unsigned& a2, unsigned& a3,
                                      unsigned addr) {
    asm volatile("ldmatrix.sync.aligned.m8n8.x4.shared.b16 {%0,%1,%2,%3},[%4];"
                 : "=r"(a0), "=r"(a1), "=r"(a2), "=r"(a3) : "r"(addr));
}
__device__ __forceinline__ void mma16816(float& c0, float& c1, float& c2, float& c3,
                                         unsigned a0, unsigned a1, unsigned a2, unsigned a3,
                                         unsigned b0, unsigned b1) {
    asm volatile("mma.sync.aligned.m16n8k16.row.col.f32.f16.f16.f32 "
                 "{%0,%1,%2,%3},{%4,%5,%6,%7},{%8,%9},{%0,%1,%2,%3};"
                 : "+f"(c0), "+f"(c1), "+f"(c2), "+f"(c3)
                 : "r"(a0), "r"(a1), "r"(a2), "r"(a3), "r"(b0), "r"(b1));
}
// Strong scoped ops: one acquire-spinner per CTA + fence-folded release arrival.
__device__ __forceinline__ unsigned ld_acq(const unsigned* p) {
    unsigned v;
    asm volatile("ld.acquire.gpu.global.u32 %0,[%1];" : "=r"(v) : "l"(p) : "memory");
    return v;
}
__device__ __forceinline__ void red_add_rel(unsigned* p, unsigned v) {
    asm volatile("red.add.release.gpu.global.u32 [%0],%1;" :: "l"(p), "r"(v) : "memory");
}
__device__ __forceinline__ uint4 ldcg_v4(const uint4* p) {
    uint4 v;
    asm volatile("ld.global.cg.v4.u32 {%0,%1,%2,%3},[%4];"
                 : "=r"(v.x), "=r"(v.y), "=r"(v.z), "=r"(v.w) : "l"(p));
    return v;
}
__device__ __forceinline__ void cta_geom(int b, int& J, int& j0) {
    if (b < 124) { J = 14; j0 = b * 14; }
    else         { J = 13; j0 = 124 * 14 + (b - 124) * 13; }
}

// packed f32x2 FMA helpers for the GEMM
__device__ __forceinline__ unsigned long long pk2(float x, float y) {
    unsigned long long r;
    asm("mov.b64 %0, {%1, %2};" : "=l"(r) : "f"(x), "f"(y));
    return r;
}
__device__ __forceinline__ void fma2(unsigned long long& a, unsigned long long m, unsigned long long n) {
    asm("fma.rn.f32x2 %0, %1, %2, %0;" : "+l"(a) : "l"(m), "l"(n));
}
__device__ __forceinline__ void upk2(unsigned long long a, float& x, float& y) {
    asm("mov.b64 {%0, %1}, %2;" : "=f"(x), "=f"(y) : "l"(a));
}

// ---------------- kernel 0: per-launch state init ----------------
__global__ void init_state(const float* __restrict__ h0) {
    int i = blockIdx.x * blockDim.x + threadIdx.x;
    if (i < H_DIM) g_hvec[0][i] = __float2half(h0[i]);
    if (i == 0) g_bar = 0u;
}

// ---------------- kernel 1: W_hh fp32 -> fp16 ----------------
__global__ void convert_whh(const float* __restrict__ W) {
    const float2* src = (const float2*)W;
    __half2* dst = (__half2*)g_whh;
    size_t n2 = (size_t)G_DIM * H_DIM / 2;
    for (size_t u = (size_t)blockIdx.x * blockDim.x + threadIdx.x; u < n2;
         u += (size_t)gridDim.x * blockDim.x) {
        float2 v = src[u];
        dst[u] = __floats2half2_rn(v.x, v.y);
    }
}

// ---------------- kernel 2: x_gates GEMM (fp32, f32x2 FMA) ----------------
__global__ void __launch_bounds__(256) gemm_xg(const float* __restrict__ A,
                                               const float* __restrict__ B,
                                               const float* __restrict__ bih,
                                               const float* __restrict__ bhh) {
    __shared__ float As[BK * LDT];
    __shared__ float Bs[BK * LDT];
    const int tid = threadIdx.x;
    const int tx = tid & 15, ty = tid >> 4;
    const int bm = blockIdx.y, bn = blockIdx.x;

    unsigned long long acc[8][4];
#pragma unroll
    for (int i = 0; i < 8; i++)
#pragma unroll
        for (int jp = 0; jp < 4; jp++) acc[i][jp] = 0ULL;

    for (int kt = 0; kt < IN_DIM; kt += BK) {
#pragma unroll
        for (int r = 0; r < 2; r++) {
            int id = tid + r * 256;
            int mr = id >> 2, kc = id & 3;
            float4 av = *(const float4*)(A + (size_t)(bm * BM + mr) * IN_DIM + kt + kc * 4);
            As[(kc * 4 + 0) * LDT + mr] = av.x;
            As[(kc * 4 + 1) * LDT + mr] = av.y;
            As[(kc * 4 + 2) * LDT + mr] = av.z;
            As[(kc * 4 + 3) * LDT + mr] = av.w;
            float4 bv = *(const float4*)(B + (size_t)(bn * BN + mr) * IN_DIM + kt + kc * 4);
            Bs[(kc * 4 + 0) * LDT + mr] = bv.x;
            Bs[(kc * 4 + 1) * LDT + mr] = bv.y;
            Bs[(kc * 4 + 2) * LDT + mr] = bv.z;
            Bs[(kc * 4 + 3) * LDT + mr] = bv.w;
        }
        __syncthreads();
#pragma unroll
        for (int k = 0; k < BK; k++) {
            float4 a0 = *(const float4*)(As + k * LDT + ty * 8);
            float4 a1 = *(const float4*)(As + k * LDT + ty * 8 + 4);
            float4 b0 = *(const float4*)(Bs + k * LDT + tx * 8);
            float4 b1 = *(const float4*)(Bs + k * LDT + tx * 8 + 4);
            unsigned long long bb0 = pk2(b0.x, b0.y);
            unsigned long long bb1 = pk2(b0.z, b0.w);
            unsigned long long bb2 = pk2(b1.x, b1.y);
            unsigned long long bb3 = pk2(b1.z, b1.w);
            float aa[8] = {a0.x, a0.y, a0.z, a0.w, a1.x, a1.y, a1.z, a1.w};
#pragma unroll
            for (int i = 0; i < 8; i++) {
                unsigned long long a2 = pk2(aa[i], aa[i]);
                fma2(acc[i][0], a2, bb0);
                fma2(acc[i][1], a2, bb1);
                fma2(acc[i][2], a2, bb2);
                fma2(acc[i][3], a2, bb3);
            }
        }
        __syncthreads();
    }

    int n0 = bn * BN + tx * 8;
    float bias[8];
#pragma unroll
    for (int u = 0; u < 8; u++) bias[u] = bih[n0 + u] + bhh[n0 + u];
#pragma unroll
    for (int i = 0; i < 8; i++) {
        int m = bm * BM + ty * 8 + i;
        float r[8];
#pragma unroll
        for (int jp = 0; jp < 4; jp++) upk2(acc[i][jp], r[2 * jp], r[2 * jp + 1]);
#pragma unroll
        for (int u = 0; u < 8; u++) r[u] += bias[u];
        float4* out = (float4*)(g_xg + (size_t)m * G_DIM + n0);
        out[0] = make_float4(r[0], r[1], r[2], r[3]);
        out[1] = make_float4(r[4], r[5], r[6], r[7]);
    }
}

// ---------------- kernel 3: persistent LSTM recurrence -----------------------
// CTA b owns units [j0, j0+J). Local row lr: gate = lr&3, unit = lr>>2;
// global W_hh row = gate*2048 + j0 + unit. Rows padded to 64.
// NEW TILING: 16 warps = 16 K-slices of 128 halves; each warp covers ALL 64
// rows (4 row-subtiles) of its slice, so one B-fragment feeds 4 MMAs
// (B smem traffic 1024 -> 256 wavefronts/step). Per warp: k16-steps 0..3 of
// its slice in registers (64 regs), steps 4..7 via ldmatrix from smem.
// Sync protocol identical to round 11 (proven).
__global__ void __launch_bounds__(NTHR, 1) lstm_recur(const float* __restrict__ c0) {
    extern __shared__ unsigned char smem_raw[];
    __half* sw    = (__half*)smem_raw;                    // [56][1032] halves (upper 64 of each 128-slice)
    __half* sh2   = (__half*)(smem_raw + SH2_OFF);        // [2048] fp16 h
    float*  sgate = (float*)(smem_raw + SGATE_OFF);       // [64][SGS] partials
    float*  sc    = (float*)(smem_raw + SC_OFF);          // [16] cell state

    const int tid  = threadIdx.x;
    const int lane = tid & 31;
    const int w    = tid >> 5;
    const int b    = blockIdx.x;

    int J, j0;
    cta_geom(b, J, j0);
    const int R = 4 * J;

    // Fill smem with the UPPER 64 halves of each 128-half K-slice, all R rows.
    for (int idx = tid; idx < R * 128; idx += NTHR) {
        int lr = idx >> 7, rem = idx & 127;
        int ks4 = rem >> 3, q = rem & 7;
        int grow = (lr & 3) * H_DIM + j0 + (lr >> 2);
        *(uint4*)((unsigned char*)sw + lr * SWROW_B + ks4 * 128 + q * 16) =
            *(const uint4*)(g_whh + (size_t)grow * H_DIM + ks4 * 128 + 64 + q * 8);
    }
    if (tid < J) sc[tid] = c0[j0 + tid];

    const int ks = w;   // this warp's K-slice (0..15)

    // A-fragments for k16-steps 0..3 of this warp's slice, all 4 row-subtiles,
    // loaded from global into registers once. arg[(s*4+st)*4 + i].
    unsigned arg[64];
    {
#pragma unroll
        for (int s = 0; s < 4; s++) {
#pragma unroll
            for (int st = 0; st < 4; st++) {
                int lr0 = 16 * st + (lane >> 2);
                int lr1 = lr0 + 8;
                if (lr0 >= R) lr0 = 0;
                if (lr1 >= R) lr1 = 0;
                int g0 = (lr0 & 3) * H_DIM + j0 + (lr0 >> 2);
                int g1 = (lr1 & 3) * H_DIM + j0 + (lr1 >> 2);
                const unsigned* p0 = (const unsigned*)(g_whh + (size_t)g0 * H_DIM)
                                   + ks * 64 + 8 * s + (lane & 3);
                const unsigned* p1 = (const unsigned*)(g_whh + (size_t)g1 * H_DIM)
                                   + ks * 64 + 8 * s + (lane & 3);
                int base = (s * 4 + st) * 4;
                arg[base + 0] = p0[0];
                arg[base + 1] = p1[0];
                arg[base + 2] = p0[4];
                arg[base + 3] = p1[4];
            }
        }
    }
    __syncthreads();

    // A-ldsm bases for smem steps (s=4..7): subtile st rows 16*st + (lane&15).
    const unsigned abase = smem_u32(sw) + (unsigned)(lane & 15) * SWROW_B
                         + (unsigned)ks * 128 + ((lane >> 4) * 16);
    int r3 = 48 + (lane & 15); if (r3 >= R) r3 = 0;      // subtile 3 clamp
    const unsigned abase3 = smem_u32(sw) + (unsigned)r3 * SWROW_B
                          + (unsigned)ks * 128 + ((lane >> 4) * 16);
    // B broadcast-ldsm base: 8-lane groups -> 4 consecutive 16B k-windows.
    const unsigned bbase = smem_u32(sh2) + (unsigned)ks * 256 + ((lane >> 3) * 16);

    int p = 0;
    for (int t = 0; t < T_STEPS; t++) {
        // x_gates prefetch for this step (independent of h; overlaps the spin).
        float xgi = 0.f, xgf = 0.f, xgg = 0.f, xgo = 0.f;
        if (tid < J) {
            const float* xg = g_xg + (size_t)t * G_DIM + j0 + tid;
            xgi = __ldcg(xg);
            xgf = __ldcg(xg + H_DIM);
            xgg = __ldcg(xg + 2 * H_DIM);
            xgo = __ldcg(xg + 3 * H_DIM);
        }
        // Wait for all CTAs' step-(t-1) publishes: ONE acquire spinner per CTA.
        if (tid == 0) {
            const unsigned target = (unsigned)t * (unsigned)NCTA;
            while (ld_acq(&g_bar) < target) { }
        }
        __syncthreads();
        // Stage h (fp16) from L2 into SMEM: 256 threads x 16 B.
        if (tid < 256) {
            uint4 v = ldcg_v4(((const uint4*)g_hvec[p]) + tid);
            *(uint4*)(sh2 + tid * 8) = v;
        }
        __syncthreads();

        // Tensor-core matvec: 8 k16-steps, 4 row-subtiles each sharing one B-frag.
        float acc[4][4];
#pragma unroll
        for (int st = 0; st < 4; st++)
#pragma unroll
            for (int i = 0; i < 4; i++) acc[st][i] = 0.f;

        // Pairs 0-1: A from registers.
#pragma unroll
        for (int pr = 0; pr < 2; pr++) {
            unsigned t0, t1, t2, t3;
            ldsm4(t0, t1, t2, t3, bbase + pr * 64);
#pragma unroll
            for (int st = 0; st < 4; st++) {
                const unsigned* a = &arg[((2 * pr) * 4 + st) * 4];
                mma16816(acc[st][0], acc[st][1], acc[st][2], acc[st][3],
                         a[0], a[1], a[2], a[3], t0, t1);
            }
#pragma unroll
            for (int st = 0; st < 4; st++) {
                const unsigned* a = &arg[((2 * pr + 1) * 4 + st) * 4];
                mma16816(acc[st][0], acc[st][1], acc[st][2], acc[st][3],
                         a[0], a[1], a[2], a[3], t2, t3);
            }
        }
        // Pairs 2-3: A from smem (steps 4..7).
#pragma unroll
        for (int pr = 0; pr < 2; pr++) {
            unsigned t0, t1, t2, t3;
            ldsm4(t0, t1, t2, t3, bbase + 128 + pr * 64);
#pragma unroll
            for (int st = 0; st < 4; st++) {
                unsigned ab = (st < 3) ? (abase + (unsigned)st * (16u * SWROW_B)) : abase3;
                unsigned a0, a1, a2, a3;
                ldsm4(a0, a1, a2, a3, ab + (2 * pr) * 32);
                mma16816(acc[st][0], acc[st][1], acc[st][2], acc[st][3],
                         a0, a1, a2, a3, t0, t1);
                ldsm4(a0, a1, a2, a3, ab + (2 * pr) * 32 + 32);
                mma16816(acc[st][0], acc[st][1], acc[st][2], acc[st][3],
                         a0, a1, a2, a3, t2, t3);
            }
        }
        // Store per-slice partials: sgate[row][ks] (all B columns identical;
        // lanes with lane%4==0 hold rows lane>>2 and +8 per subtile).
        if ((lane & 3) == 0) {
#pragma unroll
            for (int st = 0; st < 4; st++) {
                int row = 16 * st + (lane >> 2);
                if (row < R)     sgate[row * SGS + ks]       = acc[st][0];
                if (row + 8 < R) sgate[(row + 8) * SGS + ks] = acc[st][2];
            }
        }
        __syncthreads();

        // Warp-0: row-sum over 16 slices + shfl-gather gates + cell update.
        if (w == 0) {
            float s0 = 0.f, s1 = 0.f;
            {
                const float4* r0 = (const float4*)(sgate + lane * SGS);
                const float4* r1 = (const float4*)(sgate + (lane + 32) * SGS);
                float4 v0 = r0[0], v1 = r0[1], v2 = r0[2], v3 = r0[3];
                s0 = ((v0.x + v0.y) + (v0.z + v0.w)) + ((v1.x + v1.y) + (v1.z + v1.w))
                   + ((v2.x + v2.y) + (v2.z + v2.w)) + ((v3.x + v3.y) + (v3.z + v3.w));
                float4 u0 = r1[0], u1 = r1[1], u2 = r1[2], u3 = r1[3];
                s1 = ((u0.x + u0.y) + (u0.z + u0.w)) + ((u1.x + u1.y) + (u1.z + u1.w))
                   + ((u2.x + u2.y) + (u2.z + u2.w)) + ((u3.x + u3.y) + (u3.z + u3.w));
            }
            const unsigned FULL = 0xffffffffu;
            int su = (lane & 7) << 2;
            float a0 = __shfl_sync(FULL, s0, su + 0);
            float a1 = __shfl_sync(FULL, s0, su + 1);
            float a2 = __shfl_sync(FULL, s0, su + 2);
            float a3 = __shfl_sync(FULL, s0, su + 3);
            float b0 = __shfl_sync(FULL, s1, su + 0);
            float b1 = __shfl_sync(FULL, s1, su + 1);
            float b2 = __shfl_sync(FULL, s1, su + 2);
            float b3 = __shfl_sync(FULL, s1, su + 3);
            bool hi = lane >= 8;
            if (lane < J) {
                float gi = (hi ? b0 : a0) + xgi;
                float gf = (hi ? b1 : a1) + xgf;
                float gg = (hi ? b2 : a2) + xgg;
                float go = (hi ? b3 : a3) + xgo;
                float i_ = sigmoidf_(gi);
                float f_ = sigmoidf_(gf);
                float g_ = tanh_accf(gg);
                float o_ = sigmoidf_(go);
                float c = f_ * sc[lane] + i_ * g_;
                sc[lane] = c;
                float h = o_ * tanh_accf(c);
                unsigned short hs = __half_as_ushort(__float2half(h));
                asm volatile("st.global.cg.u16 [%0], %1;"
                             :: "l"(&g_hvec[p ^ 1][j0 + lane]), "h"(hs) : "memory");
            }
            __syncwarp();                        // warp-scope mem sync: h stores visible to lane 0
            if (lane == 0) red_add_rel(&g_bar, 1u);   // release elevates to gpu scope
        }
        p ^= 1;
    }
}

// ---------------- kernel 4: final linear on h_last (fp16, buffer 0) ----------
__global__ void __launch_bounds__(256) final_linear(const float* __restrict__ Wl,
                                                    const float* __restrict__ bl,
                                                    float* __restrict__ out) {
    int wid = threadIdx.x >> 5, ln = threadIdx.x & 31;
    int o = blockIdx.x * 8 + wid;
    const float4* w4 = (const float4*)(Wl + (size_t)o * H_DIM);
    const uint2* h2 = (const uint2*)g_hvec[0];
    float s = 0.f;
#pragma unroll
    for (int i = 0; i < 16; i++) {
        float4 wv = __ldg(w4 + i * 32 + ln);
        uint2 hv = h2[i * 32 + ln];
        float2 h0 = __half22float2(*(__half2*)&hv.x);
        float2 h1 = __half22float2(*(__half2*)&hv.y);
        s += wv.x * h0.x + wv.y * h0.y + wv.z * h1.x + wv.w * h1.y;
    }
#pragma unroll
    for (int sft = 16; sft >= 1; sft >>= 1) s += __shfl_xor_sync(0xffffffffu, s, sft);
    if (ln == 0) out[o] = s + bl[o];
}

// ---------------- launcher ----------------
extern "C" void kernel_launch(void* const* d_in, const int* in_sizes, int n_in,
                              void* d_out, int out_size) {
    const float* seq  = (const float*)d_in[0];
    const float* Wih  = (const float*)d_in[1];
    const float* Whh  = (const float*)d_in[2];
    const float* bih  = (const float*)d_in[3];
    const float* bhh  = (const float*)d_in[4];
    const float* h0   = (const float*)d_in[5];
    const float* c0   = (const float*)d_in[6];
    const float* Wlin = (const float*)d_in[7];
    const float* blin = (const float*)d_in[8];
    float* out = (float*)d_out;

    cudaFuncSetAttribute(lstm_recur, cudaFuncAttributeMaxDynamicSharedMemorySize, SMEM_BYTES);

    init_state<<<8, 256>>>(h0);
    convert_whh<<<2048, 256>>>(Whh);
    gemm_xg<<<dim3(G_DIM / BN, T_STEPS / BM), 256>>>(seq, Wih, bih, bhh);
    lstm_recur<<<NCTA, NTHR, SMEM_BYTES>>>(c0);
    final_linear<<<OUT_DIM / 8, 256>>>(Wlin, blin, out);
}